// round 13
// baseline (speedup 1.0000x reference)
#include <cuda_runtime.h>
#include <mma.h>
#include <math.h>
#include <stdint.h>

using namespace nvcuda;

#define S_LEN  128
#define NBATCH 2048
#define HID    128
#define G4     512
#define OUTDIM 128
#define NH     (NBATCH*HID)
#define M_ALL  (S_LEN*NBATCH)

#define WPX 132                      // W / h-tile pitch (128+4)
#define PP  68                       // park pitch (gate-major rows of 64 samples)

// ---- persist smem map (float offsets) ----
#define F_WH 0                       // [128][132] W_hh slice
#define F_WX (128*132)               // [128][132] W_ih slice
#define F_HP (2*128*132)             // union: hA tile [64][132] (8448) / hpark [128][68] (8704)
#define F_XP (F_HP + 8704)           // xpark [128][68]
#define STEP_SMEM ((F_XP + 8704)*4)  // 204800 B

// ---- proj smem map ----
#define PRJ_A  0                     // [128][132] hist tile
#define PRJ_B  (128*132)             // [128][132] W_out
#define PRJ_BT (2*128*132)           // [16][132] bias broadcast tile
#define PROJ_SMEM ((2*128*132 + 16*132)*4)   // 143616 B

#define CLUSTER_SYNC() do { \
    asm volatile("barrier.cluster.arrive.aligned;" ::: "memory"); \
    asm volatile("barrier.cluster.wait.aligned;"   ::: "memory"); \
} while (0)

// ---------------- static device scratch (no cudaMalloc anywhere) ----------------
__device__ float g_xr  [(size_t)M_ALL*HID];   // x, tf32-rounded (x-GEMM A operand, read from gmem)
__device__ float g_hist[(size_t)M_ALL*HID];   // h_t history (tf32-rounded) — h exchange medium
__device__ float g_Wih_p[G4*HID];             // packed W_ih, tf32-rounded
__device__ float g_Whh_p[G4*HID];             // packed W_hh, tf32-rounded
__device__ float g_Wout_p[OUTDIM*HID];        // W_out, tf32-rounded
__device__ float g_bp[G4];                    // b_ih + b_hh, packed row order

__device__ __forceinline__ float to_tf32(float x) {
    unsigned r;
    asm("cvt.rna.tf32.f32 %0, %1;" : "=r"(r) : "f"(x));
    return __uint_as_float(r);
}
__device__ __forceinline__ float fsigm(float v) {
    return __fdividef(1.0f, 1.0f + __expf(-v));
}
__device__ __forceinline__ float ftanh(float v) {
    return 1.0f - 2.0f*__fdividef(1.0f, 1.0f + __expf(2.0f*v));
}

// Pack: packed row r = hb*128 + gate*32 + j  <->  orig row gate*128 + hb*32 + j.
__global__ void pack_kernel(const float* __restrict__ W_ih, const float* __restrict__ W_hh,
                            const float* __restrict__ b_ih, const float* __restrict__ b_hh,
                            const float* __restrict__ W_out) {
    int idx = blockIdx.x*256 + threadIdx.x;      // 65536 = 512 rows * 128 k
    int row = idx >> 7;
    int k   = idx & 127;
    int hb = row >> 7, rem = row & 127, gate = rem >> 5, j = rem & 31;
    int orow = gate*128 + hb*32 + j;
    g_Wih_p[row*HID + k] = to_tf32(W_ih[orow*HID + k]);
    g_Whh_p[row*HID + k] = to_tf32(W_hh[orow*HID + k]);
    if (k == 0) g_bp[row] = b_ih[orow] + b_hh[orow];
    if (idx < OUTDIM*HID) g_Wout_p[idx] = to_tf32(W_out[idx]);
}

// x pre-round: g_xr = tf32(x)
__global__ void xr_kernel(const float* __restrict__ x) {
    size_t i = (size_t)blockIdx.x*256 + threadIdx.x;     // 8388608 float4
    float4 v = *((const float4*)x + i);
    float4 t = make_float4(to_tf32(v.x), to_tf32(v.y), to_tf32(v.z), to_tf32(v.w));
    *((float4*)g_xr + i) = t;
}

// ---------------- persistent recurrence: asymmetric warp specialization ----------------
// Grid (32, 4), cluster (1,4,1), 384 threads.
// Warps 0-7 (h-group): critical path — h-GEMM (K=128) + epilogue.
// Warps 8-11 (x-group): x-GEMM (K=128, A-frags from gmem) concurrently; token via bar 3.
__global__ void __launch_bounds__(384) __cluster_dims__(1, 4, 1)
lstm_persist_kernel() {
    extern __shared__ float sm[];
    float* sWh = sm + F_WH;
    float* sWx = sm + F_WX;
    float* sHP = sm + F_HP;          // hA tile / hpark union
    float* sXP = sm + F_XP;          // xpark

    const int tid = threadIdx.x;
    const int wid = tid >> 5;
    const int nb  = blockIdx.x;
    const int hb  = blockIdx.y;
    const int n0  = nb*64;

    // one-time: stage both W slices (all 384 threads)
    for (int e = tid; e < 128*32; e += 384) {
        int r = e >> 5, k4 = e & 31;
        *(float4*)&sWh[r*WPX + k4*4] = *(const float4*)(g_Whh_p + (size_t)(hb*128 + r)*HID + k4*4);
        *(float4*)&sWx[r*WPX + k4*4] = *(const float4*)(g_Wih_p + (size_t)(hb*128 + r)*HID + k4*4);
    }
    __syncthreads();

    if (tid < 256) {
        // ================= H GROUP =================
        const int wm = wid & 1;                  // 2 warp-rows (32 samples each)
        const int wn = wid >> 1;                 // 4 warp-cols (32 gate rows each)
        const int n_l = tid & 63;                // epilogue sample
        const int jg  = tid >> 6;                // epilogue j = jg*8 + q

        float c_reg[8];
        float b_i[8], b_f[8], b_g[8], b_o[8];
        #pragma unroll
        for (int q = 0; q < 8; q++) {
            int j = jg*8 + q;
            c_reg[q] = 0.0f;
            b_i[q] = g_bp[hb*128 +       j];
            b_f[q] = g_bp[hb*128 +  32 + j];
            b_g[q] = g_bp[hb*128 +  64 + j];
            b_o[q] = g_bp[hb*128 +  96 + j];
        }

        for (int s = 0; s < S_LEN; s++) {
            // ---- stage h(s-1) tile [64][132] (hist pre-tf32-rounded) ----
            if (s > 0) {
                const float* hp = g_hist + (size_t)(s-1)*NH + (size_t)n0*HID;
                #pragma unroll
                for (int i = 0; i < 8; i++) {
                    int e = tid + i*256, r = e >> 5, k4 = e & 31;
                    *(float4*)&sHP[r*WPX + k4*4] = *(const float4*)(hp + (size_t)r*HID + k4*4);
                }
            } else {
                float4 z = make_float4(0.f, 0.f, 0.f, 0.f);
                #pragma unroll
                for (int i = 0; i < 8; i++) {
                    int e = tid + i*256, r = e >> 5, k4 = e & 31;
                    *(float4*)&sHP[r*WPX + k4*4] = z;
                }
            }
            asm volatile("bar.sync 1, 256;" ::: "memory");

            // ---- h-GEMM: gates_h[64x128] = h . Whh^T, K=128 ----
            wmma::fragment<wmma::accumulator,16,16,8,float> c[2][2];
            #pragma unroll
            for (int i=0;i<2;i++) { wmma::fill_fragment(c[i][0],0.f); wmma::fill_fragment(c[i][1],0.f); }
            #pragma unroll
            for (int k = 0; k < HID; k += 8) {
                wmma::fragment<wmma::matrix_a,16,16,8,wmma::precision::tf32,wmma::row_major> a0,a1;
                wmma::fragment<wmma::matrix_b,16,16,8,wmma::precision::tf32,wmma::col_major> b0,b1;
                wmma::load_matrix_sync(a0, &sHP[(wm*32     )*WPX + k], WPX);
                wmma::load_matrix_sync(a1, &sHP[(wm*32 + 16)*WPX + k], WPX);
                wmma::load_matrix_sync(b0, &sWh[(wn*32     )*WPX + k], WPX);
                wmma::load_matrix_sync(b1, &sWh[(wn*32 + 16)*WPX + k], WPX);
                wmma::mma_sync(c[0][0], a0, b0, c[0][0]);
                wmma::mma_sync(c[0][1], a0, b1, c[0][1]);
                wmma::mma_sync(c[1][0], a1, b0, c[1][0]);
                wmma::mma_sync(c[1][1], a1, b1, c[1][1]);
            }
            asm volatile("bar.sync 1, 256;" ::: "memory");   // all h-warps done reading hA

            // ---- park gate-major over the hA region: hpark[gate_row][sample] ----
            #pragma unroll
            for (int i=0;i<2;i++)
                #pragma unroll
                for (int j=0;j<2;j++)
                    wmma::store_matrix_sync(&sHP[(wn*32 + j*16)*PP + wm*32 + i*16],
                                            c[i][j], PP, wmma::mem_col_major);

            // ---- wait for x-group's park (token), also orders hpark stores ----
            asm volatile("bar.sync 3, 384;" ::: "memory");

            // ---- elementwise LSTM (conflict-free gate-major reads), c in regs ----
            {
                float hq[8];
                #pragma unroll
                for (int q = 0; q < 8; q++) {
                    int j = jg*8 + q;
                    float iv = sXP[(      j)*PP + n_l] + sHP[(      j)*PP + n_l] + b_i[q];
                    float fv = sXP[( 32 + j)*PP + n_l] + sHP[( 32 + j)*PP + n_l] + b_f[q];
                    float gv = sXP[( 64 + j)*PP + n_l] + sHP[( 64 + j)*PP + n_l] + b_g[q];
                    float ov = sXP[( 96 + j)*PP + n_l] + sHP[( 96 + j)*PP + n_l] + b_o[q];
                    float cc = fsigm(fv)*c_reg[q] + fsigm(iv)*ftanh(gv);
                    c_reg[q] = cc;
                    hq[q] = to_tf32(fsigm(ov)*ftanh(cc));
                }
                float* hp = g_hist + (size_t)s*NH + (size_t)(n0 + n_l)*HID + hb*32 + jg*8;
                *(float4*)(hp)     = make_float4(hq[0], hq[1], hq[2], hq[3]);
                *(float4*)(hp + 4) = make_float4(hq[4], hq[5], hq[6], hq[7]);
            }

            CLUSTER_SYNC();                      // release hist[s]; frees sXP/sHP for next iter
        }
    } else {
        // ================= X GROUP =================
        const int w4 = wid - 8;
        const int wm = w4 & 1;                   // 2 warp-rows (32 samples)
        const int wn = w4 >> 1;                  // 2 warp-cols (64 gate rows)

        for (int s = 0; s < S_LEN; s++) {
            // x-GEMM: gates_x[64x128] = x(s) . Wih^T; A-frags straight from gmem
            wmma::fragment<wmma::accumulator,16,16,8,float> c[2][4];
            #pragma unroll
            for (int i=0;i<2;i++)
                #pragma unroll
                for (int j=0;j<4;j++) wmma::fill_fragment(c[i][j], 0.f);

            const float* xrow = g_xr + ((size_t)s*NBATCH + n0)*HID;
            #pragma unroll
            for (int k = 0; k < HID; k += 8) {
                wmma::fragment<wmma::matrix_a,16,16,8,wmma::precision::tf32,wmma::row_major> a0,a1;
                wmma::fragment<wmma::matrix_b,16,16,8,wmma::precision::tf32,wmma::col_major> b[4];
                wmma::load_matrix_sync(a0, xrow + (size_t)(wm*32     )*HID + k, HID);
                wmma::load_matrix_sync(a1, xrow + (size_t)(wm*32 + 16)*HID + k, HID);
                #pragma unroll
                for (int t = 0; t < 4; t++)
                    wmma::load_matrix_sync(b[t], &sWx[(wn*64 + t*16)*WPX + k], WPX);
                #pragma unroll
                for (int t = 0; t < 4; t++) {
                    wmma::mma_sync(c[0][t], a0, b[t], c[0][t]);
                    wmma::mma_sync(c[1][t], a1, b[t], c[1][t]);
                }
            }
            // park gate-major: xpark[gate_row][sample]
            #pragma unroll
            for (int i=0;i<2;i++)
                #pragma unroll
                for (int j=0;j<4;j++)
                    wmma::store_matrix_sync(&sXP[(wn*64 + j*16)*PP + wm*32 + i*16],
                                            c[i][j], PP, wmma::mem_col_major);

            asm volatile("bar.arrive 3, 384;" ::: "memory");  // token: xpark(s) ready

            CLUSTER_SYNC();
        }
    }
}

// ------------- projection: out[m][o] = hist[m][:] . W_out[o][:] + b_out[o] -------------
// 128x128 CTA tile (hist read once); acc init from bias-broadcast tile; frags stored direct to gmem.
__global__ void __launch_bounds__(256) proj_kernel(const float* __restrict__ b_out,
                                                   float* __restrict__ out) {
    extern __shared__ float sm[];
    float* sA  = sm + PRJ_A;
    float* sB  = sm + PRJ_B;
    float* sBT = sm + PRJ_BT;
    const int tid = threadIdx.x;
    const int m0  = blockIdx.x*128;

    for (int e = tid; e < 128*32; e += 256) {
        int r = e >> 5, c4 = e & 31;
        *(float4*)&sA[r*WPX + c4*4] = *(const float4*)(g_hist   + (size_t)(m0 + r)*HID + c4*4);
        *(float4*)&sB[r*WPX + c4*4] = *(const float4*)(g_Wout_p + (size_t)r*HID + c4*4);
    }
    for (int e = tid; e < 16*128; e += 256) {    // bias broadcast tile: 16 identical rows
        int r = e >> 7, col = e & 127;
        sBT[r*WPX + col] = b_out[col];
    }
    __syncthreads();

    const int w = tid >> 5;
    const int wm = w & 3, wn = w >> 2;           // 4x2 warps, warp tile 32m x 64o
    wmma::fragment<wmma::accumulator,16,16,8,float> c[2][4];
    #pragma unroll
    for (int i=0;i<2;i++)
        #pragma unroll
        for (int j=0;j<4;j++)
            wmma::load_matrix_sync(c[i][j], &sBT[wn*64 + j*16], WPX, wmma::mem_row_major);

    #pragma unroll
    for (int k = 0; k < HID; k += 8) {
        wmma::fragment<wmma::matrix_a,16,16,8,wmma::precision::tf32,wmma::row_major> a0,a1;
        wmma::fragment<wmma::matrix_b,16,16,8,wmma::precision::tf32,wmma::col_major> b[4];
        wmma::load_matrix_sync(a0, &sA[(wm*32     )*WPX + k], WPX);
        wmma::load_matrix_sync(a1, &sA[(wm*32 + 16)*WPX + k], WPX);
        #pragma unroll
        for (int t = 0; t < 4; t++)
            wmma::load_matrix_sync(b[t], &sB[(wn*64 + t*16)*WPX + k], WPX);
        #pragma unroll
        for (int t = 0; t < 4; t++) {
            wmma::mma_sync(c[0][t], a0, b[t], c[0][t]);
            wmma::mma_sync(c[1][t], a1, b[t], c[1][t]);
        }
    }
    #pragma unroll
    for (int i=0;i<2;i++)
        #pragma unroll
        for (int j=0;j<4;j++)
            wmma::store_matrix_sync(out + (size_t)(m0 + wm*32 + i*16)*OUTDIM + wn*64 + j*16,
                                    c[i][j], OUTDIM, wmma::mem_row_major);
}

extern "C" void kernel_launch(void* const* d_in, const int* in_sizes, int n_in,
                              void* d_out, int out_size) {
    const float* x     = (const float*)d_in[0];
    const float* W_ih  = (const float*)d_in[1];
    const float* W_hh  = (const float*)d_in[2];
    const float* b_ih  = (const float*)d_in[3];
    const float* b_hh  = (const float*)d_in[4];
    const float* W_out = (const float*)d_in[5];
    const float* b_out = (const float*)d_in[6];
    float* out = (float*)d_out;
    (void)in_sizes; (void)n_in; (void)out_size;

    cudaFuncSetAttribute(lstm_persist_kernel, cudaFuncAttributeMaxDynamicSharedMemorySize, STEP_SMEM);
    cudaFuncSetAttribute(proj_kernel,         cudaFuncAttributeMaxDynamicSharedMemorySize, PROJ_SMEM);

    pack_kernel<<<256, 256>>>(W_ih, W_hh, b_ih, b_hh, W_out);
    xr_kernel<<<M_ALL*HID/4/256, 256>>>(x);

    lstm_persist_kernel<<<dim3(32, 4), 384, STEP_SMEM>>>();

    proj_kernel<<<M_ALL/128, 256, PROJ_SMEM>>>(b_out, out);
}

// round 14
// speedup vs baseline: 1.2887x; 1.2887x over previous
#include <cuda_runtime.h>
#include <mma.h>
#include <math.h>
#include <stdint.h>

using namespace nvcuda;

#define S_LEN  128
#define NBATCH 2048
#define HID    128
#define G4     512
#define OUTDIM 128
#define NH     (NBATCH*HID)
#define M_ALL  (S_LEN*NBATCH)

#define TP  132                      // generic tile pitch (128+4)
#define PP  68                       // park pitch (gate-major rows of 64 samples)

// ---- persist smem map (float offsets) ----
#define F_WH 0                       // [128][132] W_hh slice              16896
#define F_HT (F_WH + 128*TP)         // [64][132]  h(s-1) tile              8448
#define F_PA (F_HT + 64*TP)          // [128][68]  park, K-half A           8704
#define F_PB (F_PA + 128*PP)         // [128][68]  park, K-half B           8704
#define F_XG (F_PB + 128*PP)         // [64][132]  xg park (sample-major)   8448
#define STEP_SMEM ((F_XG + 64*TP)*4) // 205184 B? -> (51200)*4 = 204800 B

// ---- proj smem map (float offsets) ----
#define PRJ_A  0                     // [64][132]  hist tile
#define PRJ_B  (64*TP)               // [128][132] W_out
#define PRJ_BT (PRJ_B + 128*TP)      // [16][132]  bias broadcast
#define PROJ_SMEM ((PRJ_BT + 16*TP)*4)   // 109824 B

#define CLUSTER_SYNC() do { \
    asm volatile("barrier.cluster.arrive.aligned;" ::: "memory"); \
    asm volatile("barrier.cluster.wait.aligned;"   ::: "memory"); \
} while (0)

// ---------------- static device scratch (no cudaMalloc anywhere) ----------------
__device__ float g_xg  [(size_t)M_ALL*G4];    // x·W_ih^T for all steps, packed gate cols
__device__ float g_hist[(size_t)M_ALL*HID];   // h_t history (tf32-rounded) — h exchange medium
__device__ float g_Wih_p[G4*HID];             // packed W_ih, tf32-rounded
__device__ float g_Whh_p[G4*HID];             // packed W_hh, tf32-rounded
__device__ float g_Wout_p[OUTDIM*HID];        // W_out, tf32-rounded
__device__ float g_bp[G4];                    // b_ih + b_hh, packed row order

__device__ __forceinline__ float to_tf32(float x) {
    unsigned r;
    asm("cvt.rna.tf32.f32 %0, %1;" : "=r"(r) : "f"(x));
    return __uint_as_float(r);
}
__device__ __forceinline__ float fsigm(float v) {
    return __fdividef(1.0f, 1.0f + __expf(-v));
}
__device__ __forceinline__ float ftanh(float v) {
    return 1.0f - 2.0f*__fdividef(1.0f, 1.0f + __expf(2.0f*v));
}

// Pack: packed row r = hb*128 + gate*32 + j  <->  orig row gate*128 + hb*32 + j.
__global__ void pack_kernel(const float* __restrict__ W_ih, const float* __restrict__ W_hh,
                            const float* __restrict__ b_ih, const float* __restrict__ b_hh,
                            const float* __restrict__ W_out) {
    int idx = blockIdx.x*256 + threadIdx.x;      // 65536 = 512 rows * 128 k
    int row = idx >> 7;
    int k   = idx & 127;
    int hb = row >> 7, rem = row & 127, gate = rem >> 5, j = rem & 31;
    int orow = gate*128 + hb*32 + j;
    g_Wih_p[row*HID + k] = to_tf32(W_ih[orow*HID + k]);
    g_Whh_p[row*HID + k] = to_tf32(W_hh[orow*HID + k]);
    if (k == 0) g_bp[row] = b_ih[orow] + b_hh[orow];
    if (idx < OUTDIM*HID) g_Wout_p[idx] = to_tf32(W_out[idx]);
}

// ------------- pre-GEMM: g_xg[m][g] = x[m][:] . Wih_p[g][:]  (m = s*N+n flat) -------------
// (proven round-6/12 kernel, unchanged)
__global__ void __launch_bounds__(256, 2) xg_gemm_kernel(const float* __restrict__ x) {
    extern __shared__ float sm[];
    float* sA = sm;                 // [128][TP]
    float* sB = sm + 128*TP;        // [64][TP]
    const int tid = threadIdx.x;
    const int m0 = blockIdx.x*128;
    const int n0 = blockIdx.y*64;

    const float* xr = x + (size_t)m0*HID;
    for (int e = tid; e < 128*32; e += 256) {
        int r = e >> 5, c4 = e & 31;
        float4 v = *(const float4*)(xr + (size_t)r*HID + c4*4);
        float* d = &sA[r*TP + c4*4];
        d[0]=to_tf32(v.x); d[1]=to_tf32(v.y); d[2]=to_tf32(v.z); d[3]=to_tf32(v.w);
    }
    for (int e = tid; e < 64*32; e += 256) {
        int r = e >> 5, c4 = e & 31;
        *(float4*)&sB[r*TP + c4*4] = *(const float4*)(g_Wih_p + (size_t)(n0+r)*HID + c4*4);
    }
    __syncthreads();

    const int w = tid >> 5;
    const int wm = w & 3, wn = w >> 2;          // 4x2 warp grid
    wmma::fragment<wmma::accumulator,16,16,8,float> c[2][2];
    #pragma unroll
    for (int i=0;i<2;i++) { wmma::fill_fragment(c[i][0],0.f); wmma::fill_fragment(c[i][1],0.f); }

    #pragma unroll
    for (int k = 0; k < HID; k += 8) {
        wmma::fragment<wmma::matrix_a,16,16,8,wmma::precision::tf32,wmma::row_major> a0,a1;
        wmma::fragment<wmma::matrix_b,16,16,8,wmma::precision::tf32,wmma::col_major> b0,b1;
        wmma::load_matrix_sync(a0, &sA[(wm*32     )*TP + k], TP);
        wmma::load_matrix_sync(a1, &sA[(wm*32 + 16)*TP + k], TP);
        wmma::load_matrix_sync(b0, &sB[(wn*32     )*TP + k], TP);
        wmma::load_matrix_sync(b1, &sB[(wn*32 + 16)*TP + k], TP);
        wmma::mma_sync(c[0][0], a0, b0, c[0][0]);
        wmma::mma_sync(c[0][1], a0, b1, c[0][1]);
        wmma::mma_sync(c[1][0], a1, b0, c[1][0]);
        wmma::mma_sync(c[1][1], a1, b1, c[1][1]);
    }
    #pragma unroll
    for (int i=0;i<2;i++)
        #pragma unroll
        for (int j=0;j<2;j++)
            wmma::store_matrix_sync(&g_xg[(size_t)(m0 + wm*32 + i*16)*G4 + n0 + wn*32 + j*16],
                                    c[i][j], G4, wmma::mem_row_major);
}

// ---------------- persistent recurrence: h-GEMM only (K=128), xg streamed from gmem ----------------
// Grid (32, 4), cluster (1,4,1), 512 threads.
// Warps 0-7: K-half [0,64) -> sPA. Warps 8-15: K-half [64,128) -> sPB.
// xg(s) coalesced-LDG'd at loop top (latency hides under stage+GEMM), STS'd before epilogue.
__global__ void __launch_bounds__(512) __cluster_dims__(1, 4, 1)
lstm_persist_kernel() {
    extern __shared__ float sm[];
    float* sWh = sm + F_WH;
    float* sHT = sm + F_HT;
    float* sPA = sm + F_PA;
    float* sPB = sm + F_PB;
    float* sXG = sm + F_XG;

    const int tid = threadIdx.x;
    const int wid = tid >> 5;
    const int nb  = blockIdx.x;
    const int hb  = blockIdx.y;
    const int n0  = nb*64;

    // one-time: W_hh slice
    for (int e = tid; e < 128*32; e += 512) {
        int r = e >> 5, k4 = e & 31;
        *(float4*)&sWh[r*TP + k4*4] = *(const float4*)(g_Whh_p + (size_t)(hb*128 + r)*HID + k4*4);
    }

    const int  w8 = wid & 7;
    const int  wm = w8 & 1;                     // 2 warp-rows (32 samples)
    const int  wn = w8 >> 1;                    // 4 warp-cols (32 gate rows)
    const int  k0 = (wid < 8) ? 0 : 64;
    float* myPark = (wid < 8) ? sPA : sPB;

    const int n_l = tid & 63;                   // epilogue: owned sample
    const int jg  = tid >> 6;                   // 0..7; epilogue j = jg*4 + q

    float c_reg[4] = {0.f, 0.f, 0.f, 0.f};
    float b_i[4], b_f[4], b_g[4], b_o[4];       // bias direct to regs (L2)
    #pragma unroll
    for (int q = 0; q < 4; q++) {
        int j = jg*4 + q;
        b_i[q] = g_bp[hb*128 +       j];
        b_f[q] = g_bp[hb*128 +  32 + j];
        b_g[q] = g_bp[hb*128 +  64 + j];
        b_o[q] = g_bp[hb*128 +  96 + j];
    }
    __syncthreads();                            // sWh ready

    for (int s = 0; s < S_LEN; s++) {
        // ---- issue coalesced xg(s) loads early; consumed after the GEMM ----
        float4 xgv[4];
        {
            const float* xgrow = g_xg + ((size_t)s*NBATCH + n0)*G4 + hb*128;
            #pragma unroll
            for (int i = 0; i < 4; i++) {
                int e = tid + i*512, r = e >> 5, c4 = e & 31;
                xgv[i] = *(const float4*)(xgrow + (size_t)r*G4 + c4*4);
            }
        }
        // ---- stage h(s-1) tile (hist pre-tf32-rounded) ----
        if (s > 0) {
            const float* hp = g_hist + (size_t)(s-1)*NH + (size_t)n0*HID;
            #pragma unroll
            for (int i = 0; i < 4; i++) {
                int e = tid + i*512, r = e >> 5, k4 = e & 31;
                *(float4*)&sHT[r*TP + k4*4] = *(const float4*)(hp + (size_t)r*HID + k4*4);
            }
        } else {
            float4 z = make_float4(0.f, 0.f, 0.f, 0.f);
            #pragma unroll
            for (int i = 0; i < 4; i++) {
                int e = tid + i*512, r = e >> 5, k4 = e & 31;
                *(float4*)&sHT[r*TP + k4*4] = z;
            }
        }
        __syncthreads();

        // ---- h-GEMM, my K-half (no intra-step group barriers: parks are dedicated bufs) ----
        {
            wmma::fragment<wmma::accumulator,16,16,8,float> c[2][2];
            #pragma unroll
            for (int i=0;i<2;i++) { wmma::fill_fragment(c[i][0],0.f); wmma::fill_fragment(c[i][1],0.f); }
            #pragma unroll
            for (int kk = 0; kk < 64; kk += 8) {
                const int k = k0 + kk;
                wmma::fragment<wmma::matrix_a,16,16,8,wmma::precision::tf32,wmma::row_major> a0,a1;
                wmma::fragment<wmma::matrix_b,16,16,8,wmma::precision::tf32,wmma::col_major> b0,b1;
                wmma::load_matrix_sync(a0, &sHT[(wm*32     )*TP + k], TP);
                wmma::load_matrix_sync(a1, &sHT[(wm*32 + 16)*TP + k], TP);
                wmma::load_matrix_sync(b0, &sWh[(wn*32     )*TP + k], TP);
                wmma::load_matrix_sync(b1, &sWh[(wn*32 + 16)*TP + k], TP);
                wmma::mma_sync(c[0][0], a0, b0, c[0][0]);
                wmma::mma_sync(c[0][1], a0, b1, c[0][1]);
                wmma::mma_sync(c[1][0], a1, b0, c[1][0]);
                wmma::mma_sync(c[1][1], a1, b1, c[1][1]);
            }
            // park gate-major: park[gate_row][sample]
            #pragma unroll
            for (int i=0;i<2;i++)
                #pragma unroll
                for (int j=0;j<2;j++)
                    wmma::store_matrix_sync(&myPark[(wn*32 + j*16)*PP + wm*32 + i*16],
                                            c[i][j], PP, wmma::mem_col_major);
        }
        // ---- land xg into its park (sample-major) ----
        #pragma unroll
        for (int i = 0; i < 4; i++) {
            int e = tid + i*512, r = e >> 5, c4 = e & 31;
            *(float4*)&sXG[r*TP + c4*4] = xgv[i];
        }
        __syncthreads();

        // ---- elementwise LSTM: xg(f4) + parkA + parkB + bias; c in regs ----
        {
            const float* xgr = &sXG[n_l*TP];
            float4 xi = *(const float4*)&xgr[      jg*4];
            float4 xf = *(const float4*)&xgr[ 32 + jg*4];
            float4 xg_ = *(const float4*)&xgr[ 64 + jg*4];
            float4 xo = *(const float4*)&xgr[ 96 + jg*4];
            float xiq[4] = {xi.x, xi.y, xi.z, xi.w};
            float xfq[4] = {xf.x, xf.y, xf.z, xf.w};
            float xgq[4] = {xg_.x, xg_.y, xg_.z, xg_.w};
            float xoq[4] = {xo.x, xo.y, xo.z, xo.w};

            float hq[4];
            #pragma unroll
            for (int q = 0; q < 4; q++) {
                int j = jg*4 + q;
                float iv = xiq[q] + sPA[(      j)*PP + n_l] + sPB[(      j)*PP + n_l] + b_i[q];
                float fv = xfq[q] + sPA[( 32 + j)*PP + n_l] + sPB[( 32 + j)*PP + n_l] + b_f[q];
                float gv = xgq[q] + sPA[( 64 + j)*PP + n_l] + sPB[( 64 + j)*PP + n_l] + b_g[q];
                float ov = xoq[q] + sPA[( 96 + j)*PP + n_l] + sPB[( 96 + j)*PP + n_l] + b_o[q];
                float cc = fsigm(fv)*c_reg[q] + fsigm(iv)*ftanh(gv);
                c_reg[q] = cc;
                hq[q] = to_tf32(fsigm(ov)*ftanh(cc));
            }
            float* hp = g_hist + (size_t)s*NH + (size_t)(n0 + n_l)*HID + hb*32 + jg*4;
            *(float4*)hp = make_float4(hq[0], hq[1], hq[2], hq[3]);
        }

        CLUSTER_SYNC();                         // release hist[s]; full step barrier
    }
}

// ------------- projection: out[m][o] = hist[m][:] . W_out[o][:] + b_out[o] -------------
// 64m x 128o tile: hist read ONCE; acc init from bias tile; frags stored direct to gmem.
__global__ void __launch_bounds__(256, 2) proj_kernel(const float* __restrict__ b_out,
                                                      float* __restrict__ out) {
    extern __shared__ float sm[];
    float* sA  = sm + PRJ_A;        // [64][TP]
    float* sB  = sm + PRJ_B;        // [128][TP]
    float* sBT = sm + PRJ_BT;       // [16][TP]
    const int tid = threadIdx.x;
    const int m0  = blockIdx.x*64;

    for (int e = tid; e < 64*32; e += 256) {
        int r = e >> 5, c4 = e & 31;
        *(float4*)&sA[r*TP + c4*4] = *(const float4*)(g_hist + (size_t)(m0 + r)*HID + c4*4);
    }
    for (int e = tid; e < 128*32; e += 256) {
        int r = e >> 5, c4 = e & 31;
        *(float4*)&sB[r*TP + c4*4] = *(const float4*)(g_Wout_p + (size_t)r*HID + c4*4);
    }
    for (int e = tid; e < 16*128; e += 256) {
        int r = e >> 7, col = e & 127;
        sBT[r*TP + col] = b_out[col];
    }
    __syncthreads();

    const int w = tid >> 5;
    const int wm = w & 1, wn = w >> 1;          // 2x4 warps, warp tile 32m x 32o
    wmma::fragment<wmma::accumulator,16,16,8,float> c[2][2];
    #pragma unroll
    for (int i=0;i<2;i++)
        #pragma unroll
        for (int j=0;j<2;j++)
            wmma::load_matrix_sync(c[i][j], &sBT[wn*32 + j*16], TP, wmma::mem_row_major);

    #pragma unroll
    for (int k = 0; k < HID; k += 8) {
        wmma::fragment<wmma::matrix_a,16,16,8,wmma::precision::tf32,wmma::row_major> a0,a1;
        wmma::fragment<wmma::matrix_b,16,16,8,wmma::precision::tf32,wmma::col_major> b0,b1;
        wmma::load_matrix_sync(a0, &sA[(wm*32     )*TP + k], TP);
        wmma::load_matrix_sync(a1, &sA[(wm*32 + 16)*TP + k], TP);
        wmma::load_matrix_sync(b0, &sB[(wn*32     )*TP + k], TP);
        wmma::load_matrix_sync(b1, &sB[(wn*32 + 16)*TP + k], TP);
        wmma::mma_sync(c[0][0], a0, b0, c[0][0]);
        wmma::mma_sync(c[0][1], a0, b1, c[0][1]);
        wmma::mma_sync(c[1][0], a1, b0, c[1][0]);
        wmma::mma_sync(c[1][1], a1, b1, c[1][1]);
    }
    #pragma unroll
    for (int i=0;i<2;i++)
        #pragma unroll
        for (int j=0;j<2;j++)
            wmma::store_matrix_sync(out + (size_t)(m0 + wm*32 + i*16)*OUTDIM + wn*32 + j*16,
                                    c[i][j], OUTDIM, wmma::mem_row_major);
}

extern "C" void kernel_launch(void* const* d_in, const int* in_sizes, int n_in,
                              void* d_out, int out_size) {
    const float* x     = (const float*)d_in[0];
    const float* W_ih  = (const float*)d_in[1];
    const float* W_hh  = (const float*)d_in[2];
    const float* b_ih  = (const float*)d_in[3];
    const float* b_hh  = (const float*)d_in[4];
    const float* W_out = (const float*)d_in[5];
    const float* b_out = (const float*)d_in[6];
    float* out = (float*)d_out;
    (void)in_sizes; (void)n_in; (void)out_size;

    cudaFuncSetAttribute(xg_gemm_kernel,      cudaFuncAttributeMaxDynamicSharedMemorySize, ((128+64)*TP + 0)*4);
    cudaFuncSetAttribute(lstm_persist_kernel, cudaFuncAttributeMaxDynamicSharedMemorySize, STEP_SMEM);
    cudaFuncSetAttribute(proj_kernel,         cudaFuncAttributeMaxDynamicSharedMemorySize, PROJ_SMEM);

    pack_kernel<<<256, 256>>>(W_ih, W_hh, b_ih, b_hh, W_out);
    xg_gemm_kernel<<<dim3(M_ALL/128, G4/64), 256, (128+64)*TP*4>>>(x);

    lstm_persist_kernel<<<dim3(32, 4), 512, STEP_SMEM>>>();

    proj_kernel<<<M_ALL/64, 256, PROJ_SMEM>>>(b_out, out);
}

// round 15
// speedup vs baseline: 1.3675x; 1.0611x over previous
#include <cuda_runtime.h>
#include <mma.h>
#include <math.h>
#include <stdint.h>

using namespace nvcuda;

#define S_LEN  128
#define NBATCH 2048
#define HID    128
#define G4     512
#define OUTDIM 128
#define NH     (NBATCH*HID)
#define M_ALL  (S_LEN*NBATCH)      // 262144

#define TP   132                   // k-major tile pitch (128+4)
#define HP   132                   // h tile pitch
#define PKP  36                    // park pitch (32 samples + 4)

// ---- persist smem map (float offsets): total 51456 floats = 205824 B ----
#define F_W   0                    // [256][132] W_hh slice (my p half)
#define F_H0  (256*TP)             // [32][132]  h tile, buffer 0
#define F_H1  (F_H0 + 32*HP)       // [32][132]  h tile, buffer 1
#define F_PK  (F_H1 + 32*HP)       // [256][36]  gate park
#define STEP_SMEM ((F_PK + 256*PKP)*4)

// ---- xg kernel smem: sA[64][132] + sB[64][132] + park[64][132] = 101376 B ----
#define XG_SMEM (3*64*TP*4)

// ---- proj smem: sAT[128][68] + sB[128][132] + sBT[16][132] = 110848 B ----
#define PAP 68
#define PRJ_AT 0
#define PRJ_B  (128*PAP)
#define PRJ_BT (PRJ_B + 128*TP)
#define PROJ_SMEM ((PRJ_BT + 16*TP)*4)

#define CLUSTER_SYNC() do { \
    asm volatile("barrier.cluster.arrive.aligned;" ::: "memory"); \
    asm volatile("barrier.cluster.wait.aligned;"   ::: "memory"); \
} while (0)

// ---------------- static device scratch (no cudaMalloc anywhere) ----------------
__device__ float4 g_xg4[(size_t)(G4/4)*M_ALL];  // xg, gate-quad-major: [gq][m] float4  (536 MB)
__device__ float  g_histT[(size_t)HID*M_ALL];   // h history, TRANSPOSED [hcol][m]      (134 MB)
__device__ float  g_Wih_p2[G4*HID];             // W_ih, pair-packed, tf32-rounded
__device__ float  g_Whh_p2[G4*HID];             // W_hh, pair-packed, tf32-rounded
__device__ float  g_Wout_p[OUTDIM*HID];         // W_out, tf32-rounded
__device__ float  g_bp2[G4];                    // b_ih + b_hh, pair-packed order

__device__ __forceinline__ float to_tf32(float x) {
    unsigned r;
    asm("cvt.rna.tf32.f32 %0, %1;" : "=r"(r) : "f"(x));
    return __uint_as_float(r);
}
__device__ __forceinline__ float fsigm(float v) {
    return __fdividef(1.0f, 1.0f + __expf(-v));
}
__device__ __forceinline__ float ftanh(float v) {
    return 1.0f - 2.0f*__fdividef(1.0f, 1.0f + __expf(2.0f*v));
}
__device__ __forceinline__ uint32_t smem_u32(const void* p) {
    uint32_t a;
    asm("{ .reg .u64 t; cvta.to.shared.u64 t, %1; cvt.u32.u64 %0, t; }" : "=r"(a) : "l"(p));
    return a;
}

// Pair-packing: packed row g = p*256 + gate*64 + jj  <->  orig row gate*128 + p*64 + jj.
__global__ void pack_kernel(const float* __restrict__ W_ih, const float* __restrict__ W_hh,
                            const float* __restrict__ b_ih, const float* __restrict__ b_hh,
                            const float* __restrict__ W_out) {
    int idx = blockIdx.x*256 + threadIdx.x;      // 65536 = 512 rows * 128 k
    int g = idx >> 7;
    int k = idx & 127;
    int p = g >> 8, rem = g & 255, gate = rem >> 6, jj = rem & 63;
    int orow = gate*128 + p*64 + jj;
    g_Wih_p2[g*HID + k] = to_tf32(W_ih[orow*HID + k]);
    g_Whh_p2[g*HID + k] = to_tf32(W_hh[orow*HID + k]);
    if (k == 0) g_bp2[g] = b_ih[orow] + b_hh[orow];
    if (idx < OUTDIM*HID) g_Wout_p[idx] = to_tf32(W_out[idx]);
}

// ------------- xg pre-GEMM: xg[g][m] = x[m][:] . Wih_p2[g][:], stored gate-quad float4 -------------
// Grid 4096 m-blocks of 64; x tile read ONCE; loop 8 chunks of 64 packed gate rows.
__global__ void __launch_bounds__(256, 2) xg_gemm_kernel(const float* __restrict__ x) {
    extern __shared__ float sm[];
    float* sA  = sm;                // [64][132] x tile (tf32)
    float* sB  = sm + 64*TP;        // [64][132] W_ih chunk
    float* sPk = sm + 128*TP;       // [64][132] chunk park (col_major: [g_local][m])
    const int tid = threadIdx.x;
    const int m0  = blockIdx.x*64;

    for (int e = tid; e < 64*32; e += 256) {
        int r = e >> 5, c4 = e & 31;
        float4 v = *(const float4*)(x + (size_t)(m0 + r)*HID + c4*4);
        float* d = &sA[r*TP + c4*4];
        d[0]=to_tf32(v.x); d[1]=to_tf32(v.y); d[2]=to_tf32(v.z); d[3]=to_tf32(v.w);
    }
    __syncthreads();

    const int w = tid >> 5;
    const int wm = w & 1, wn = w >> 1;          // 2m x 4n warps; warp tile m32 x n16

    for (int c = 0; c < 8; c++) {
        for (int e = tid; e < 64*32; e += 256) {
            int r = e >> 5, c4 = e & 31;
            *(float4*)&sB[r*TP + c4*4] =
                *(const float4*)(g_Wih_p2 + (size_t)(c*64 + r)*HID + c4*4);
        }
        __syncthreads();

        wmma::fragment<wmma::accumulator,16,16,8,float> acc[2];
        wmma::fill_fragment(acc[0], 0.f); wmma::fill_fragment(acc[1], 0.f);
        #pragma unroll
        for (int k = 0; k < HID; k += 8) {
            wmma::fragment<wmma::matrix_a,16,16,8,wmma::precision::tf32,wmma::row_major> a0,a1;
            wmma::fragment<wmma::matrix_b,16,16,8,wmma::precision::tf32,wmma::col_major> b0;
            wmma::load_matrix_sync(a0, &sA[(wm*32     )*TP + k], TP);
            wmma::load_matrix_sync(a1, &sA[(wm*32 + 16)*TP + k], TP);
            wmma::load_matrix_sync(b0, &sB[(wn*16     )*TP + k], TP);
            wmma::mma_sync(acc[0], a0, b0, acc[0]);
            wmma::mma_sync(acc[1], a1, b0, acc[1]);
        }
        // park col_major: park[g_local][m], ldm = TP
        wmma::store_matrix_sync(&sPk[(wn*16)*TP + wm*32     ], acc[0], TP, wmma::mem_col_major);
        wmma::store_matrix_sync(&sPk[(wn*16)*TP + wm*32 + 16], acc[1], TP, wmma::mem_col_major);
        __syncthreads();

        // STG pass: gate-quad float4 layout g_xg4[gq][m]
        for (int e = tid; e < 16*64; e += 256) {
            int gq_l = e >> 6, mm = e & 63;
            float4 v = make_float4(sPk[(gq_l*4 + 0)*TP + mm], sPk[(gq_l*4 + 1)*TP + mm],
                                   sPk[(gq_l*4 + 2)*TP + mm], sPk[(gq_l*4 + 3)*TP + mm]);
            g_xg4[(size_t)(c*16 + gq_l)*M_ALL + m0 + mm] = v;
        }
        __syncthreads();                         // park + sB free for next chunk
    }
}

// ---------------- persistent recurrence: cluster-pair, h resident in SMEM ----------------
// Grid (64, 2), cluster (1,2,1), 512 threads. CTA p owns gate rows [256p, 256p+256)
// = h cols [64p, 64p+64) for the cluster's 32 samples. h exchanged via DSMEM; no staging.
__global__ void __launch_bounds__(512) __cluster_dims__(1, 2, 1)
lstm_persist_kernel() {
    extern __shared__ float sm[];
    float* sW  = sm + F_W;
    float* sH[2] = { sm + F_H0, sm + F_H1 };
    float* sPk = sm + F_PK;

    const int tid  = threadIdx.x;
    const int wid  = tid >> 5;
    const int lane = tid & 31;
    const int nb   = blockIdx.x;
    const int p    = blockIdx.y;                // cluster rank
    const int n0   = nb*32;

    // one-time: W slice (256 rows x 128 k), zero both h buffers
    for (int e = tid; e < 256*32; e += 512) {
        int r = e >> 5, c4 = e & 31;
        *(float4*)&sW[r*TP + c4*4] = *(const float4*)(g_Whh_p2 + (size_t)(p*256 + r)*HID + c4*4);
    }
    for (int e = tid; e < 32*HP; e += 512) { sH[0][e] = 0.f; sH[1][e] = 0.f; }

    // epilogue ownership: lane = sample, warp jg -> cols jg*4..+3 (of my 64)
    const int jg = wid;                          // 0..15
    float bb[16];
    #pragma unroll
    for (int g = 0; g < 4; g++)
        #pragma unroll
        for (int q = 0; q < 4; q++)
            bb[g*4 + q] = g_bp2[p*256 + g*64 + jg*4 + q];
    float c_reg[4] = {0.f, 0.f, 0.f, 0.f};

    // GEMM warp coords: 2m x 8n, warp tile m16 x n32
    const int wm = wid & 1;
    const int wn = wid >> 1;

    __syncthreads();
    CLUSTER_SYNC();                              // peer's h buffers zeroed before any DSMEM write

    for (int s = 0; s < S_LEN; s++) {
        float* hc = sH[s & 1];
        float* hn = sH[(s & 1) ^ 1];

        // ---- xg(s): 4 coalesced LDG.128, consumed after GEMM ----
        float4 xv[4];
        #pragma unroll
        for (int g = 0; g < 4; g++)
            xv[g] = g_xg4[(size_t)(p*64 + g*16 + jg)*M_ALL + (size_t)s*NBATCH + n0 + lane];

        // ---- GEMM: gates[32 x 256] = h . W^T, K=128, h already in smem ----
        wmma::fragment<wmma::accumulator,16,16,8,float> acc[2];
        wmma::fill_fragment(acc[0], 0.f); wmma::fill_fragment(acc[1], 0.f);
        #pragma unroll
        for (int k = 0; k < HID; k += 8) {
            wmma::fragment<wmma::matrix_a,16,16,8,wmma::precision::tf32,wmma::row_major> a0;
            wmma::fragment<wmma::matrix_b,16,16,8,wmma::precision::tf32,wmma::col_major> b0,b1;
            wmma::load_matrix_sync(a0, &hc[(wm*16)*HP + k], HP);
            wmma::load_matrix_sync(b0, &sW[(wn*32     )*TP + k], TP);
            wmma::load_matrix_sync(b1, &sW[(wn*32 + 16)*TP + k], TP);
            wmma::mma_sync(acc[0], a0, b0, acc[0]);
            wmma::mma_sync(acc[1], a0, b1, acc[1]);
        }
        // park col_major: park[gate_row][sample], pitch 36
        wmma::store_matrix_sync(&sPk[(wn*32     )*PKP + wm*16], acc[0], PKP, wmma::mem_col_major);
        wmma::store_matrix_sync(&sPk[(wn*32 + 16)*PKP + wm*16], acc[1], PKP, wmma::mem_col_major);
        __syncthreads();

        // ---- elementwise LSTM (park reads conflict-free: lane spans 32 banks) ----
        float hq[4];
        const float* xvf = (const float*)xv;
        #pragma unroll
        for (int q = 0; q < 4; q++) {
            int rj = jg*4 + q;
            float iv = sPk[(      rj)*PKP + lane] + xvf[ 0 + q] + bb[ 0 + q];
            float fv = sPk[( 64 + rj)*PKP + lane] + xvf[ 4 + q] + bb[ 4 + q];
            float gv = sPk[(128 + rj)*PKP + lane] + xvf[ 8 + q] + bb[ 8 + q];
            float ov = sPk[(192 + rj)*PKP + lane] + xvf[12 + q] + bb[12 + q];
            float cc = fsigm(fv)*c_reg[q] + fsigm(iv)*ftanh(gv);
            c_reg[q] = cc;
            hq[q] = to_tf32(fsigm(ov)*ftanh(cc));
        }

        // ---- write h: own tile (STS.128), peer tile (DSMEM), hist (coalesced transposed) ----
        float* hdst = &hn[lane*HP + p*64 + jg*4];
        *(float4*)hdst = make_float4(hq[0], hq[1], hq[2], hq[3]);
        {
            uint32_t la = smem_u32(hdst), ra;
            asm("mapa.shared::cluster.u32 %0, %1, %2;" : "=r"(ra) : "r"(la), "r"(p ^ 1));
            asm volatile("st.shared::cluster.f32 [%0],    %1;" :: "r"(ra), "f"(hq[0]) : "memory");
            asm volatile("st.shared::cluster.f32 [%0+4],  %1;" :: "r"(ra), "f"(hq[1]) : "memory");
            asm volatile("st.shared::cluster.f32 [%0+8],  %1;" :: "r"(ra), "f"(hq[2]) : "memory");
            asm volatile("st.shared::cluster.f32 [%0+12], %1;" :: "r"(ra), "f"(hq[3]) : "memory");
        }
        {
            size_t hb0 = (size_t)(p*64 + jg*4)*M_ALL + (size_t)s*NBATCH + n0 + lane;
            g_histT[hb0            ] = hq[0];
            g_histT[hb0 +   M_ALL  ] = hq[1];
            g_histT[hb0 + 2*(size_t)M_ALL] = hq[2];
            g_histT[hb0 + 3*(size_t)M_ALL] = hq[3];
        }

        CLUSTER_SYNC();   // full step barrier; publishes DSMEM h + guards park/hc reuse
    }
}

// ------------- projection: out[m][o] = histT[:, m] . W_out[o][:] + b_out[o] -------------
// 64m x 128o tile; A staged k-major from histT (coalesced), col_major A frags.
__global__ void __launch_bounds__(256, 2) proj_kernel(const float* __restrict__ b_out,
                                                      float* __restrict__ out) {
    extern __shared__ float sm[];
    float* sAT = sm + PRJ_AT;       // [128 k][68 m]
    float* sB  = sm + PRJ_B;        // [128 o][132 k]
    float* sBT = sm + PRJ_BT;       // [16][132] bias broadcast
    const int tid = threadIdx.x;
    const int m0  = blockIdx.x*64;

    for (int e = tid; e < 128*16; e += 256) {
        int kk = e >> 4, m4 = e & 15;
        *(float4*)&sAT[kk*PAP + m4*4] =
            *(const float4*)(g_histT + (size_t)kk*M_ALL + m0 + m4*4);
    }
    for (int e = tid; e < 128*32; e += 256) {
        int r = e >> 5, c4 = e & 31;
        *(float4*)&sB[r*TP + c4*4] = *(const float4*)(g_Wout_p + (size_t)r*HID + c4*4);
    }
    for (int e = tid; e < 16*128; e += 256) {
        int r = e >> 7, col = e & 127;
        sBT[r*TP + col] = b_out[col];
    }
    __syncthreads();

    const int w = tid >> 5;
    const int wm = w & 1, wn = w >> 1;          // 2m x 4n, warp tile m32 x n32
    wmma::fragment<wmma::accumulator,16,16,8,float> c[2][2];
    #pragma unroll
    for (int i = 0; i < 2; i++)
        #pragma unroll
        for (int j = 0; j < 2; j++)
            wmma::load_matrix_sync(c[i][j], &sBT[wn*32 + j*16], TP, wmma::mem_row_major);

    #pragma unroll
    for (int k = 0; k < HID; k += 8) {
        wmma::fragment<wmma::matrix_a,16,16,8,wmma::precision::tf32,wmma::col_major> a0,a1;
        wmma::fragment<wmma::matrix_b,16,16,8,wmma::precision::tf32,wmma::col_major> b0,b1;
        wmma::load_matrix_sync(a0, &sAT[k*PAP + wm*32     ], PAP);
        wmma::load_matrix_sync(a1, &sAT[k*PAP + wm*32 + 16], PAP);
        wmma::load_matrix_sync(b0, &sB[(wn*32     )*TP + k], TP);
        wmma::load_matrix_sync(b1, &sB[(wn*32 + 16)*TP + k], TP);
        wmma::mma_sync(c[0][0], a0, b0, c[0][0]);
        wmma::mma_sync(c[0][1], a0, b1, c[0][1]);
        wmma::mma_sync(c[1][0], a1, b0, c[1][0]);
        wmma::mma_sync(c[1][1], a1, b1, c[1][1]);
    }
    #pragma unroll
    for (int i = 0; i < 2; i++)
        #pragma unroll
        for (int j = 0; j < 2; j++)
            wmma::store_matrix_sync(out + (size_t)(m0 + wm*32 + i*16)*OUTDIM + wn*32 + j*16,
                                    c[i][j], OUTDIM, wmma::mem_row_major);
}

extern "C" void kernel_launch(void* const* d_in, const int* in_sizes, int n_in,
                              void* d_out, int out_size) {
    const float* x     = (const float*)d_in[0];
    const float* W_ih  = (const float*)d_in[1];
    const float* W_hh  = (const float*)d_in[2];
    const float* b_ih  = (const float*)d_in[3];
    const float* b_hh  = (const float*)d_in[4];
    const float* W_out = (const float*)d_in[5];
    const float* b_out = (const float*)d_in[6];
    float* out = (float*)d_out;
    (void)in_sizes; (void)n_in; (void)out_size;

    cudaFuncSetAttribute(xg_gemm_kernel,      cudaFuncAttributeMaxDynamicSharedMemorySize, XG_SMEM);
    cudaFuncSetAttribute(lstm_persist_kernel, cudaFuncAttributeMaxDynamicSharedMemorySize, STEP_SMEM);
    cudaFuncSetAttribute(proj_kernel,         cudaFuncAttributeMaxDynamicSharedMemorySize, PROJ_SMEM);

    pack_kernel<<<256, 256>>>(W_ih, W_hh, b_ih, b_hh, W_out);
    xg_gemm_kernel<<<M_ALL/64, 256, XG_SMEM>>>(x);

    lstm_persist_kernel<<<dim3(64, 2), 512, STEP_SMEM>>>();

    proj_kernel<<<M_ALL/64, 256, PROJ_SMEM>>>(b_out, out);
}

// round 17
// speedup vs baseline: 3.6706x; 2.6842x over previous
#include <cuda_runtime.h>
#include <mma.h>
#include <cuda_fp16.h>
#include <math.h>
#include <stdint.h>

using namespace nvcuda;

#define S_LEN  128
#define NBATCH 2048
#define HID    128
#define G4     512
#define OUTDIM 128
#define M_ALL  (S_LEN*NBATCH)      // 262144

#define HWP 136                    // half-tile pitch in halves (128+8); row = 272 B
#define PKP 20                     // persist park pitch, floats (16 samples + 4)

// ---- persist smem (bytes): sW 69632 | sH0 4352 | sH1 4352 | sPk 20480 = 98816 ----
#define PS_W   0
#define PS_H0  69632
#define PS_H1  73984
#define PS_PK  78336
#define STEP_SMEM 98816

// ---- xg smem: sX 17408 | sW 17408 | sPkF 17408 = 52224 ----
#define XG_X   0
#define XG_W   17408
#define XG_PK  34816
#define XG_SMEM 52224

// ---- proj smem: sAT 18432 | sB 34816 | sBT 8448 = 61696 ----
#define PJ_AT  0
#define PJ_B   18432
#define PJ_BT  53248
#define PROJ_SMEM 61696
#define PAP 72                     // proj A pitch (halves): 64 m + 8

#define CLUSTER_SYNC() do { \
    asm volatile("barrier.cluster.arrive.aligned;" ::: "memory"); \
    asm volatile("barrier.cluster.wait.aligned;"   ::: "memory"); \
} while (0)

// ---------------- static device scratch (no cudaMalloc anywhere) ----------------
__device__ uint2  g_xgq [(size_t)HID*M_ALL];   // xg gate-quads (i,f,g,o) fp16: [hcol][m]  268 MB
__device__ __half g_histTh[(size_t)HID*M_ALL]; // h history fp16, transposed [hcol][m]      67 MB
__device__ __half g_Whh_h[G4*HID];             // W_hh, gate-interleaved pack, fp16
__device__ __half g_Wih_h[G4*HID];             // W_ih, gate-interleaved pack, fp16
__device__ __half g_Wout_h[OUTDIM*HID];        // W_out fp16
__device__ float  g_bp2[G4];                   // b_ih + b_hh, packed order

__device__ __forceinline__ float fsigm(float v) {
    return __fdividef(1.0f, 1.0f + __expf(-v));
}
__device__ __forceinline__ float ftanh(float v) {
    return 1.0f - 2.0f*__fdividef(1.0f, 1.0f + __expf(2.0f*v));
}
__device__ __forceinline__ uint32_t smem_u32(const void* p) {
    uint32_t a;
    asm("{ .reg .u64 t; cvta.to.shared.u64 t, %1; cvt.u32.u64 %0, t; }" : "=r"(a) : "l"(p));
    return a;
}

// Gate-interleaved pair-pack: packed row g2 = p*256 + jj*4 + gate
//   <-> orig row gate*128 + p*64 + jj.   (p = hcol half, jj = local hcol)
__global__ void pack_kernel(const float* __restrict__ W_ih, const float* __restrict__ W_hh,
                            const float* __restrict__ b_ih, const float* __restrict__ b_hh,
                            const float* __restrict__ W_out) {
    int idx = blockIdx.x*256 + threadIdx.x;      // 65536 = 512 rows * 128 k
    int g2 = idx >> 7;
    int k  = idx & 127;
    int p = g2 >> 8, r = g2 & 255, jj = r >> 2, gate = r & 3;
    int orow = gate*128 + p*64 + jj;
    g_Whh_h[g2*HID + k] = __float2half(W_hh[orow*HID + k]);
    g_Wih_h[g2*HID + k] = __float2half(W_ih[orow*HID + k]);
    if (k == 0) g_bp2[g2] = b_ih[orow] + b_hh[orow];
    if (idx < OUTDIM*HID) g_Wout_h[idx] = __float2half(W_out[idx]);
}

// ------------- xg pre-GEMM: xg[g2][m] = x[m][:] . Wih[g2][:]; out = fp16 gate-quads -------------
// Grid 4096 m-tiles of 64. x tile resident (fp16); 8 chunks of 64 packed rows = one (p, jj-block).
__global__ void __launch_bounds__(256, 3) xg_gemm_kernel(const float* __restrict__ x) {
    extern __shared__ char smem[];
    __half* sX  = (__half*)(smem + XG_X);    // [64][136]
    __half* sW  = (__half*)(smem + XG_W);    // [64][136]
    float*  sPk = (float*)(smem + XG_PK);    // [64][68] chunk park (col-major: [g_local][m])
    const int tid = threadIdx.x;
    const int m0  = blockIdx.x*64;

    for (int e = tid; e < 64*32; e += 256) {
        int r = e >> 5, c4 = e & 31;
        float4 v = *(const float4*)(x + (size_t)(m0 + r)*HID + c4*4);
        __half2 lo = __floats2half2_rn(v.x, v.y);
        __half2 hi = __floats2half2_rn(v.z, v.w);
        ((__half2*)(sX + r*HWP))[c4*2    ] = lo;
        ((__half2*)(sX + r*HWP))[c4*2 + 1] = hi;
    }
    __syncthreads();

    const int w = tid >> 5;
    const int wm = w & 1, wn = w >> 1;       // 2m x 4n warps; warp m32 x n16

    for (int c = 0; c < 8; c++) {
        for (int e = tid; e < 64*32; e += 256) {          // W chunk (fp16, coalesced)
            int r = e >> 5, c4 = e & 31;
            ((uint2*)(sW + r*HWP))[c4] =
                ((const uint2*)(g_Wih_h + (size_t)(c*64 + r)*HID))[c4];
        }
        __syncthreads();

        wmma::fragment<wmma::accumulator,16,16,16,float> acc[2];
        wmma::fill_fragment(acc[0], 0.f); wmma::fill_fragment(acc[1], 0.f);
        #pragma unroll
        for (int k = 0; k < HID; k += 16) {
            wmma::fragment<wmma::matrix_a,16,16,16,__half,wmma::row_major> a0, a1;
            wmma::fragment<wmma::matrix_b,16,16,16,__half,wmma::col_major> b0;
            wmma::load_matrix_sync(a0, sX + (wm*32     )*HWP + k, HWP);
            wmma::load_matrix_sync(a1, sX + (wm*32 + 16)*HWP + k, HWP);
            wmma::load_matrix_sync(b0, sW + (wn*16     )*HWP + k, HWP);
            wmma::mma_sync(acc[0], a0, b0, acc[0]);
            wmma::mma_sync(acc[1], a1, b0, acc[1]);
        }
        wmma::store_matrix_sync(&sPk[(wn*16)*68 + wm*32     ], acc[0], 68, wmma::mem_col_major);
        wmma::store_matrix_sync(&sPk[(wn*16)*68 + wm*32 + 16], acc[1], 68, wmma::mem_col_major);
        __syncthreads();

        // STG: build fp16 quads; chunk c -> p = c>>2, jj block (c&3)*16
        for (int e = tid; e < 16*64; e += 256) {
            int jj_l = e >> 6, m = e & 63;
            float f0 = sPk[(jj_l*4 + 0)*68 + m];
            float f1 = sPk[(jj_l*4 + 1)*68 + m];
            float f2 = sPk[(jj_l*4 + 2)*68 + m];
            float f3 = sPk[(jj_l*4 + 3)*68 + m];
            __half2 lo = __floats2half2_rn(f0, f1);
            __half2 hi = __floats2half2_rn(f2, f3);
            uint2 val = make_uint2(*(unsigned*)&lo, *(unsigned*)&hi);
            int col = (c >> 2)*64 + (c & 3)*16 + jj_l;
            g_xgq[(size_t)col*M_ALL + m0 + m] = val;
        }
        __syncthreads();
    }
}

// ---------------- persistent recurrence: fp16 operands, 2 CTAs/SM, 128 independent clusters ----------------
// Grid (128, 2), cluster (1,2,1), 512 threads, 2 blocks/SM.
// Cluster = 16 samples; CTA p computes hcols [64p, 64p+64) (256 gate rows), K=128 over h.
__global__ void __launch_bounds__(512, 2) __cluster_dims__(1, 2, 1)
lstm_persist_kernel() {
    extern __shared__ char smem[];
    __half* sW  = (__half*)(smem + PS_W);    // [256][136] W_hh slice
    __half* sH0 = (__half*)(smem + PS_H0);   // [16][136] h buf 0
    __half* sH1 = (__half*)(smem + PS_H1);   // [16][136] h buf 1
    float*  sPk = (float*)(smem + PS_PK);    // [256][20] park (gate-interleaved rows)

    const int tid = threadIdx.x;
    const int wid = tid >> 5;
    const int nb  = blockIdx.x;
    const int p   = blockIdx.y;
    const int n0  = nb*16;

    // one-time: W slice (fp16, coalesced), zero both h buffers
    for (int e = tid; e < 256*32; e += 512) {
        int r = e >> 5, c4 = e & 31;
        ((uint2*)(sW + r*HWP))[c4] =
            ((const uint2*)(g_Whh_h + (size_t)(p*256 + r)*HID))[c4];
    }
    for (int e = tid; e < 2176; e += 512)     // both h buffers = 8704 B contiguous
        ((unsigned*)(smem + PS_H0))[e] = 0u;

    // epilogue mapping: n_l = sample, jg -> cols jg*2, jg*2+1
    const int n_l = tid & 15;
    const int jg  = tid >> 4;                 // 0..31
    float bb[8];
    #pragma unroll
    for (int cc = 0; cc < 2; cc++)
        #pragma unroll
        for (int g = 0; g < 4; g++)
            bb[cc*4 + g] = g_bp2[p*256 + (jg*2 + cc)*4 + g];
    float c_reg[2] = {0.f, 0.f};

    __syncthreads();
    CLUSTER_SYNC();                           // peer h buffers zeroed before any DSMEM write

    const size_t colA = (size_t)(p*64 + jg*2    )*M_ALL;
    const size_t colB = (size_t)(p*64 + jg*2 + 1)*M_ALL;

    for (int s = 0; s < S_LEN; s++) {
        __half* hc = (s & 1) ? sH1 : sH0;
        __half* hn = (s & 1) ? sH0 : sH1;
        const size_t mG = (size_t)s*NBATCH + n0 + n_l;

        // xg quads: 2 coalesced LDG.64, consumed after GEMM
        uint2 xq0 = g_xgq[colA + mG];
        uint2 xq1 = g_xgq[colB + mG];

        // GEMM: gates[16 x 256] = h[16x128] . W^T ; 16 warps, warp tile m16 x n16
        wmma::fragment<wmma::accumulator,16,16,16,float> acc;
        wmma::fill_fragment(acc, 0.f);
        #pragma unroll
        for (int k = 0; k < HID; k += 16) {
            wmma::fragment<wmma::matrix_a,16,16,16,__half,wmma::row_major> a;
            wmma::fragment<wmma::matrix_b,16,16,16,__half,wmma::col_major> b;
            wmma::load_matrix_sync(a, hc + k, HWP);
            wmma::load_matrix_sync(b, sW + (wid*16)*HWP + k, HWP);
            wmma::mma_sync(acc, a, b, acc);
        }
        wmma::store_matrix_sync(&sPk[(wid*16)*PKP], acc, PKP, wmma::mem_col_major);
        __syncthreads();

        // epilogue: 2 cols per thread; gates are quad rows j*4+{i,f,g,o}
        __half hh[2];
        #pragma unroll
        for (int cc = 0; cc < 2; cc++) {
            int j = jg*2 + cc;
            const uint2& xq = cc ? xq1 : xq0;
            __half2 xlo = *(const __half2*)&xq.x;     // (i, f)
            __half2 xhi = *(const __half2*)&xq.y;     // (g, o)
            float2 xif = __half22float2(xlo);
            float2 xgo = __half22float2(xhi);
            float iv = sPk[(j*4 + 0)*PKP + n_l] + xif.x + bb[cc*4 + 0];
            float fv = sPk[(j*4 + 1)*PKP + n_l] + xif.y + bb[cc*4 + 1];
            float gv = sPk[(j*4 + 2)*PKP + n_l] + xgo.x + bb[cc*4 + 2];
            float ov = sPk[(j*4 + 3)*PKP + n_l] + xgo.y + bb[cc*4 + 3];
            float c  = fsigm(fv)*c_reg[cc] + fsigm(iv)*ftanh(gv);
            c_reg[cc] = c;
            hh[cc] = __float2half(fsigm(ov)*ftanh(c));
        }
        __half2 hv = __halves2half2(hh[0], hh[1]);

        // write h: own tile + peer tile (DSMEM) + hist (fp16, transposed, coalesced)
        int hidx = n_l*68 + p*32 + jg;           // half2 index: (n_l*136 + p*64 + jg*2)/2
        ((__half2*)hn)[hidx] = hv;
        {
            uint32_t la = smem_u32(&((__half2*)hn)[hidx]), ra;
            asm("mapa.shared::cluster.u32 %0, %1, %2;" : "=r"(ra) : "r"(la), "r"(p ^ 1));
            asm volatile("st.shared::cluster.u32 [%0], %1;" :: "r"(ra), "r"(*(unsigned*)&hv) : "memory");
        }
        g_histTh[colA + mG] = hh[0];
        g_histTh[colB + mG] = hh[1];

        CLUSTER_SYNC();                          // publish h(s); step barrier (park/tile reuse)
    }
}

// ------------- projection: out[m][o] = histT[:, m] . W_out[o][:] + b_out[o] (fp16 ops) -------------
__global__ void __launch_bounds__(256, 2) proj_kernel(const float* __restrict__ b_out,
                                                      float* __restrict__ out) {
    extern __shared__ char smem[];
    __half* sAT = (__half*)(smem + PJ_AT);   // [128 k][72 m]
    __half* sB  = (__half*)(smem + PJ_B);    // [128 o][136 k]
    float*  sBT = (float*)(smem + PJ_BT);    // [16][132] bias broadcast
    const int tid = threadIdx.x;
    const int m0  = blockIdx.x*64;

    for (int e = tid; e < 128*16; e += 256) {
        int kk = e >> 4, m4 = e & 15;
        ((uint2*)(sAT + kk*PAP))[m4] =
            ((const uint2*)(g_histTh + (size_t)kk*M_ALL + m0))[m4];
    }
    for (int e = tid; e < 128*32; e += 256) {
        int r = e >> 5, c4 = e & 31;
        ((uint2*)(sB + r*HWP))[c4] = ((const uint2*)(g_Wout_h + (size_t)r*HID))[c4];
    }
    for (int e = tid; e < 16*128; e += 256) {
        int r = e >> 7, col = e & 127;
        sBT[r*132 + col] = b_out[col];
    }
    __syncthreads();

    const int w = tid >> 5;
    const int wm = w & 1, wn = w >> 1;       // 2m x 4n warps, warp m32 x n32
    wmma::fragment<wmma::accumulator,16,16,16,float> c[2][2];
    #pragma unroll
    for (int i = 0; i < 2; i++)
        #pragma unroll
        for (int j = 0; j < 2; j++)
            wmma::load_matrix_sync(c[i][j], &sBT[wn*32 + j*16], 132, wmma::mem_row_major);

    #pragma unroll
    for (int k = 0; k < HID; k += 16) {
        wmma::fragment<wmma::matrix_a,16,16,16,__half,wmma::col_major> a0, a1;
        wmma::fragment<wmma::matrix_b,16,16,16,__half,wmma::col_major> b0, b1;
        wmma::load_matrix_sync(a0, sAT + k*PAP + wm*32,      PAP);
        wmma::load_matrix_sync(a1, sAT + k*PAP + wm*32 + 16, PAP);
        wmma::load_matrix_sync(b0, sB + (wn*32     )*HWP + k, HWP);
        wmma::load_matrix_sync(b1, sB + (wn*32 + 16)*HWP + k, HWP);
        wmma::mma_sync(c[0][0], a0, b0, c[0][0]);
        wmma::mma_sync(c[0][1], a0, b1, c[0][1]);
        wmma::mma_sync(c[1][0], a1, b0, c[1][0]);
        wmma::mma_sync(c[1][1], a1, b1, c[1][1]);
    }
    #pragma unroll
    for (int i = 0; i < 2; i++)
        #pragma unroll
        for (int j = 0; j < 2; j++)
            wmma::store_matrix_sync(out + (size_t)(m0 + wm*32 + i*16)*OUTDIM + wn*32 + j*16,
                                    c[i][j], OUTDIM, wmma::mem_row_major);
}

extern "C" void kernel_launch(void* const* d_in, const int* in_sizes, int n_in,
                              void* d_out, int out_size) {
    const float* x     = (const float*)d_in[0];
    const float* W_ih  = (const float*)d_in[1];
    const float* W_hh  = (const float*)d_in[2];
    const float* b_ih  = (const float*)d_in[3];
    const float* b_hh  = (const float*)d_in[4];
    const float* W_out = (const float*)d_in[5];
    const float* b_out = (const float*)d_in[6];
    float* out = (float*)d_out;
    (void)in_sizes; (void)n_in; (void)out_size;

    cudaFuncSetAttribute(xg_gemm_kernel,      cudaFuncAttributeMaxDynamicSharedMemorySize, XG_SMEM);
    cudaFuncSetAttribute(lstm_persist_kernel, cudaFuncAttributeMaxDynamicSharedMemorySize, STEP_SMEM);
    cudaFuncSetAttribute(proj_kernel,         cudaFuncAttributeMaxDynamicSharedMemorySize, PROJ_SMEM);

    pack_kernel<<<256, 256>>>(W_ih, W_hh, b_ih, b_hh, W_out);
    xg_gemm_kernel<<<M_ALL/64, 256, XG_SMEM>>>(x);

    lstm_persist_kernel<<<dim3(128, 2), 512, STEP_SMEM>>>();

    proj_kernel<<<M_ALL/64, 256, PROJ_SMEM>>>(b_out, out);
}